// round 11
// baseline (speedup 1.0000x reference)
#include <cuda_runtime.h>
#include <cuda_fp16.h>
#include <math.h>

#define NEGV (-1e30f)

constexpr int C        = 256;
constexpr int LMAX     = 128;
constexpr int THREADS  = 1024;  // 32 warps, 8/SMSP
constexpr int MAXB     = 64;
constexpr int P16PITCH = 264;   // halves per fp16 p copy (132 words ≡ 4 mod 32)
constexpr int GRID_PAD = 148;

__device__ float g_f  [MAXB][C];
__device__ float g_g  [MAXB][C];
__device__ float g_a  [MAXB][LMAX];
__device__ float g_bt [MAXB][LMAX];
__device__ float g_lsf[MAXB];
__device__ float g_lsg[MAXB];
__device__ int   g_bar = 0;     // last-CTA ticket; reset by the combiner every call

struct SmemLayout {
  __half p16[2][8 * P16PITCH];    // fp16 p, 8 bank-shifted copies, double-buffered (8.4KB)
  float  xt[2][C];                // x_t tiles for numerator gather + exp factors
  float  nb[2][LMAX + 2];         // numerator DP (log domain)
  float  red[32];
  float  sc[MAXB];                // per-batch scores (combine phase)
  int    labs[LMAX];
  int    amLast;
};

__device__ __forceinline__ float lse2_fast(float a, float b) {
  float mx = fmaxf(a, b);
  float mn = fminf(a, b);
  return mx + __logf(1.0f + __expf(mn - mx));
}

__global__ void __launch_bounds__(THREADS, 1)
chain_kernel(const float* __restrict__ x, const float* __restrict__ trans,
             const int* __restrict__ labels, const int* __restrict__ durations,
             int T, int L, int nwork, int grid, int B,
             float* __restrict__ out, int out_size)
{
  extern __shared__ char smraw[];
  SmemLayout& sm = *reinterpret_cast<SmemLayout*>(smraw);

  const int  tid  = threadIdx.x;
  const int  lane = tid & 31;
  const int  w    = tid >> 5;

  if (blockIdx.x < (unsigned)nwork) {
    const int  b    = blockIdx.x >> 1;
    const bool bwd  = blockIdx.x & 1;

    const int jp = w * 4 + (lane >> 3);   // j-pair 0..127
    const int h  = lane & 7;              // c-eighth (32 c each)
    const int j0 = 2 * jp, j1 = j0 + 1;
    const int cbase = h * 32;

    const int D      = durations[b];
    const int m      = D >> 1;
    const int nsteps = bwd ? (D - 1 - m) : m;
    const int dt     = bwd ? -1 : 1;
    int t            = bwd ? (D - 1) : 1;

    // ---- M slice in fp16 registers: 32 c (c-paired half2) x 2 j
    __half2 mA[16], mB[16];
    #pragma unroll
    for (int k = 0; k < 16; ++k) {
      int c0 = cbase + 2 * k, c1 = c0 + 1;
      float a0, a1, b0, b1;
      if (!bwd) {
        a0 = __expf(trans[c0 * C + j0]); a1 = __expf(trans[c1 * C + j0]);
        b0 = __expf(trans[c0 * C + j1]); b1 = __expf(trans[c1 * C + j1]);
      } else {
        a0 = __expf(trans[j0 * C + c0]); a1 = __expf(trans[j0 * C + c1]);
        b0 = __expf(trans[j1 * C + c0]); b1 = __expf(trans[j1 * C + c1]);
      }
      mA[k] = __floats2half2_rn(a0, a1);
      mB[k] = __floats2half2_rn(b0, b1);
    }
    for (int l = tid; l < L; l += THREADS) sm.labs[l] = labels[b * L + l];

    const float* xb = x + (size_t)b * T * C;

    // ---- init p16 (8 copies), red, xt, nb
    if (tid < C) {
      int tp = bwd ? (D - 1) : 0;
      float w0 = __expf(xb[(size_t)tp * C + tid]);
      #pragma unroll
      for (int cp = 0; cp < 8; ++cp)
        sm.p16[0][cp * P16PITCH + tid] = __float2half_rn(w0);
      sm.xt[0][tid] = xb[(size_t)t * C + tid];
    }
    { // red init: per-warp sums of w0 over this warp's owned entries (h==0 lanes)
      float rv = 0.0f;
      if (h == 0 && tid < THREADS) {
        int tp = bwd ? (D - 1) : 0;
        rv = __expf(xb[(size_t)tp * C + j0]) + __expf(xb[(size_t)tp * C + j1]);
      }
      rv += __shfl_xor_sync(0xffffffffu, rv, 8);
      rv += __shfl_xor_sync(0xffffffffu, rv, 16);
      if (lane == 0) sm.red[w] = rv;
    }
    if (tid < LMAX + 2) { sm.nb[0][tid] = NEGV; sm.nb[1][tid] = NEGV; }
    __syncthreads();
    if (tid == 0) {
      if (!bwd) sm.nb[0][1] = xb[sm.labs[0]];
      else      sm.nb[0][L] = 0.0f;
    }

    float xc0 = xb[(size_t)t * C + j0];
    float xc1 = xb[(size_t)t * C + j0 + 1];

    float logS = 0.0f;
    int   cur  = 0;
    float wn0 = 0.0f, wn1 = 0.0f;

    const bool isnum = (h == 1);
    const int  lnum  = jp;
    int lab0 = 0, lab1 = -1;
    if (isnum && lnum < L) {
      lab0 = sm.labs[lnum];
      lab1 = (lnum + 1 < L) ? sm.labs[lnum + 1] : -1;
    }

    // read: copy h, c offset 32h -> halves 264h + 32h = 296h (word 148h, 16B aligned)
    const int prdoff = 296 * h;
    const int pwroff = h * P16PITCH + j0;

    for (int k = 0; k < nsteps; ++k) {
      __syncthreads();   // p16[cur], xt[cur], nb[cur], red visible
      const bool more = (k + 1) < nsteps;
      const int  nxt  = cur ^ 1;

      float pf0 = 0.0f, pf1 = 0.0f;
      if (more) {
        float2 xn = *reinterpret_cast<const float2*>(xb + (size_t)(t + dt) * C + j0);
        pf0 = xn.x; pf1 = xn.y;
      }

      // ---- lagged normalizer (previous step's sum over 32 warps)
      float S = sm.red[lane];
      #pragma unroll
      for (int o = 16; o; o >>= 1) S += __shfl_xor_sync(0xffffffffu, S, o);
      float rs = __fdividef(1.0f, S);

      // ---- GEMV eighth: 4 LDS.128 of p16 + 32 register-operand HFMA2
      const uint4* ph = reinterpret_cast<const uint4*>(sm.p16[cur] + prdoff);
      __half2 a0 = __float2half2_rn(0.0f), a1 = a0, b0 = a0, b1 = a0;
      #pragma unroll
      for (int q = 0; q < 4; ++q) {
        uint4 pm = ph[q];
        const __half2* p2 = reinterpret_cast<const __half2*>(&pm);
        a0 = __hfma2(p2[0], mA[4 * q + 0], a0);
        a1 = __hfma2(p2[1], mA[4 * q + 1], a1);
        a0 = __hfma2(p2[2], mA[4 * q + 2], a0);
        a1 = __hfma2(p2[3], mA[4 * q + 3], a1);
        b0 = __hfma2(p2[0], mB[4 * q + 0], b0);
        b1 = __hfma2(p2[1], mB[4 * q + 1], b1);
        b0 = __hfma2(p2[2], mB[4 * q + 2], b0);
        b1 = __hfma2(p2[3], mB[4 * q + 3], b1);
      }
      float2 fa0 = __half22float2(a0), fa1 = __half22float2(a1);
      float2 fb0 = __half22float2(b0), fb1 = __half22float2(b1);
      float y0 = (fa0.x + fa0.y) + (fa1.x + fa1.y);
      float y1 = (fb0.x + fb0.y) + (fb1.x + fb1.y);
      // combine 8 h-eighths (symmetric within the 8-lane group)
      y0 += __shfl_xor_sync(0xffffffffu, y0, 1);
      y0 += __shfl_xor_sync(0xffffffffu, y0, 2);
      y0 += __shfl_xor_sync(0xffffffffu, y0, 4);
      y1 += __shfl_xor_sync(0xffffffffu, y1, 1);
      y1 += __shfl_xor_sync(0xffffffffu, y1, 2);
      y1 += __shfl_xor_sync(0xffffffffu, y1, 4);

      if (!bwd) {
        wn0 = y0 * __expf(xc0) * rs;
        wn1 = y1 * __expf(xc1) * rs;
      } else {
        wn0 = y0 * rs;
        wn1 = y1 * rs;
        if (more) { wn0 *= __expf(pf0); wn1 *= __expf(pf1); }
      }
      *reinterpret_cast<__half2*>(&sm.p16[nxt][pwroff]) =
          __floats2half2_rn(wn0, wn1);

      { // per-step red: sum of h==0 lanes' (wn0+wn1) within the warp
        float rv = (h == 0) ? (wn0 + wn1) : 0.0f;
        rv += __shfl_xor_sync(0xffffffffu, rv, 8);
        rv += __shfl_xor_sync(0xffffffffu, rv, 16);
        if (lane == 0) sm.red[w] = rv;
      }

      if (h == 2 && more)
        *reinterpret_cast<float2*>(&sm.xt[nxt][j0]) = make_float2(pf0, pf1);

      if (isnum && lnum < L) {
        int l = lnum;
        float nnew;
        if (!bwd) {
          float e = sm.xt[cur][lab0];
          nnew = lse2_fast(sm.nb[cur][l + 1], sm.nb[cur][l]) + e;
        } else {
          float v0 = sm.nb[cur][l + 1] + sm.xt[cur][lab0];
          float v1 = NEGV;
          if (lab1 >= 0) v1 = sm.nb[cur][l + 2] + sm.xt[cur][lab1];
          nnew = lse2_fast(v0, v1);
        }
        sm.nb[nxt][l + 1] = nnew;
      }

      if (tid == 0) logS += __logf(S);

      xc0 = pf0; xc1 = pf1;
      cur ^= 1;
      t   += dt;
    }
    __syncthreads();

    float Sf = sm.red[lane];
    #pragma unroll
    for (int o = 16; o; o >>= 1) Sf += __shfl_xor_sync(0xffffffffu, Sf, o);

    if (!bwd) {
      if (h == 0) {   // final w held in registers (identical across h lanes)
        g_f[b][j0] = wn0 / Sf;
        g_f[b][j1] = wn1 / Sf;
      }
      if (tid < L)  g_a[b][tid] = sm.nb[cur][tid + 1];
      if (tid == 0) g_lsf[b] = logS + logf(Sf);
    } else {
      if (h == 0) {
        g_g[b][j0] = wn0 / Sf;
        g_g[b][j1] = wn1 / Sf;
      }
      if (tid < L)  g_bt[b][tid] = sm.nb[cur][tid + 1];
      if (tid == 0) g_lsg[b] = logS + logf(Sf);
    }
    __syncthreads();
  }

  // ---- last-CTA-done: the final arriver performs the combine ----
  if (tid == 0) {
    __threadfence();                       // release g_f/g_a/g_lsf...
    int ticket = atomicAdd(&g_bar, 1);
    sm.amLast = (ticket == grid - 1);
  }
  __syncthreads();
  if (!sm.amLast) return;
  __threadfence();                         // acquire others' writes

  // combine (warp per batch)
  for (int b2 = w; b2 < B; b2 += 32) {
    float dot = 0.0f;
    for (int c = lane; c < C; c += 32) dot += g_f[b2][c] * g_g[b2][c];
    #pragma unroll
    for (int o = 16; o; o >>= 1) dot += __shfl_xor_sync(0xffffffffu, dot, o);

    float mx = -INFINITY;
    for (int l = lane; l < L; l += 32) mx = fmaxf(mx, g_a[b2][l] + g_bt[b2][l]);
    #pragma unroll
    for (int o = 16; o; o >>= 1) mx = fmaxf(mx, __shfl_xor_sync(0xffffffffu, mx, o));

    float s = 0.0f;
    for (int l = lane; l < L; l += 32) s += expf(g_a[b2][l] + g_bt[b2][l] - mx);
    #pragma unroll
    for (int o = 16; o; o >>= 1) s += __shfl_xor_sync(0xffffffffu, s, o);

    if (lane == 0) {
      float num = mx + logf(s);
      float den = logf(dot) + g_lsf[b2] + g_lsg[b2];
      sm.sc[b2] = num - den;
    }
  }
  __syncthreads();
  if (tid == 0) {
    float tot = 0.0f;
    for (int i = 0; i < B; ++i) tot += sm.sc[i];   // fixed order => deterministic
    long long fr = 0;
    for (int i = 0; i < B; ++i) fr += durations[i];
    out[0] = tot;
    if (out_size > 1) out[1] = (float)fr;
    if (out_size > 2) out[2] = (float)fr;
    g_bar = 0;                                     // reset for next (graph) call
    __threadfence();
  }
}

extern "C" void kernel_launch(void* const* d_in, const int* in_sizes, int n_in,
                              void* d_out, int out_size)
{
  const float* x      = (const float*)d_in[0];
  const float* trans  = (const float*)d_in[1];
  const int*   labels = (const int*)d_in[2];
  const int*   dur    = (const int*)d_in[3];

  int B = in_sizes[3];
  int L = in_sizes[2] / B;
  int T = in_sizes[0] / (B * C);
  int nwork = 2 * B;
  int grid  = nwork < GRID_PAD ? GRID_PAD : nwork;

  size_t smem = sizeof(SmemLayout);
  cudaFuncSetAttribute(chain_kernel, cudaFuncAttributeMaxDynamicSharedMemorySize, (int)smem);

  chain_kernel<<<grid, THREADS, smem>>>(x, trans, labels, dur, T, L,
                                        nwork, grid, B, (float*)d_out, out_size);
}

// round 12
// speedup vs baseline: 1.4576x; 1.4576x over previous
#include <cuda_runtime.h>
#include <cuda_fp16.h>
#include <math.h>

#define NEGV (-1e30f)

constexpr int C        = 256;
constexpr int LMAX     = 128;
constexpr int THREADS  = 512;   // 16 warps (R10 sweet spot)
constexpr int MAXB     = 64;
constexpr int P16PITCH = 272;   // halves per fp16 p copy (reads & writes bank-conflict-free)
constexpr int GRID_PAD = 148;

__device__ float g_f  [MAXB][C];
__device__ float g_g  [MAXB][C];
__device__ float g_a  [MAXB][LMAX];
__device__ float g_bt [MAXB][LMAX];
__device__ float g_lsf[MAXB];
__device__ float g_lsg[MAXB];
__device__ int   g_bar = 0;     // last-CTA ticket; reset by the combiner every call

struct SmemLayout {
  __half p16[2][4 * P16PITCH];    // fp16 p, 4 bank-shifted copies, double-buffered
  float  xt[2][C];                // x_t tiles for numerator gather
  float  nb[2][LMAX + 2];         // numerator DP (log domain)
  float  red[16];
  float  sc[MAXB];                // per-batch scores (combine phase)
  int    labs[LMAX];
  int    amLast;
};

__device__ __forceinline__ float lse2_fast(float a, float b) {
  float mx = fmaxf(a, b);
  float mn = fminf(a, b);
  return mx + __logf(1.0f + __expf(mn - mx));
}

__global__ void __launch_bounds__(THREADS, 1)
chain_kernel(const float* __restrict__ x, const float* __restrict__ trans,
             const int* __restrict__ labels, const int* __restrict__ durations,
             int T, int L, int nwork, int grid, int B,
             float* __restrict__ out, int out_size)
{
  extern __shared__ char smraw[];
  SmemLayout& sm = *reinterpret_cast<SmemLayout*>(smraw);

  const int  tid  = threadIdx.x;
  const int  lane = tid & 31;
  const int  w    = tid >> 5;

  if (blockIdx.x < (unsigned)nwork) {
    const int  b    = blockIdx.x >> 1;
    const bool bwd  = blockIdx.x & 1;

    const int jp = w * 8 + (lane >> 2);   // j-pair 0..127
    const int h  = lane & 3;              // c-quarter
    const int j0 = 2 * jp, j1 = j0 + 1;
    const int cbase = h * 64;             // this thread's c range: [cbase, cbase+64)

    const int D      = durations[b];
    const int m      = D >> 1;
    const int nsteps = bwd ? (D - 1 - m) : m;
    const int dt     = bwd ? -1 : 1;
    const int t0     = bwd ? (D - 1) : 1;     // u_k = t0 + dt*k

    // ---- ALL of M in fp16 registers: 64 c (c-paired half2) x 2 j
    __half2 mA[32], mB[32];
    #pragma unroll
    for (int k = 0; k < 32; ++k) {
      int c0 = cbase + 2 * k, c1 = c0 + 1;
      float a0, a1, b0, b1;
      if (!bwd) {
        a0 = __expf(trans[c0 * C + j0]); a1 = __expf(trans[c1 * C + j0]);
        b0 = __expf(trans[c0 * C + j1]); b1 = __expf(trans[c1 * C + j1]);
      } else {
        a0 = __expf(trans[j0 * C + c0]); a1 = __expf(trans[j0 * C + c1]);
        b0 = __expf(trans[j1 * C + c0]); b1 = __expf(trans[j1 * C + c1]);
      }
      mA[k] = __floats2half2_rn(a0, a1);
      mB[k] = __floats2half2_rn(b0, b1);
    }
    for (int l = tid; l < L; l += THREADS) sm.labs[l] = labels[b * L + l];

    const float* xb = x + (size_t)b * T * C;

    // ---- init p16 (4 copies), red, xt, nb
    if (tid < C) {
      int tp = bwd ? (D - 1) : 0;
      float w0 = __expf(xb[(size_t)tp * C + tid]);
      #pragma unroll
      for (int cp = 0; cp < 4; ++cp)
        sm.p16[0][cp * P16PITCH + tid] = __float2half_rn(w0);
      sm.xt[0][tid] = xb[(size_t)t0 * C + tid];
      float rv = w0;
      #pragma unroll
      for (int o = 16; o; o >>= 1) rv += __shfl_xor_sync(0xffffffffu, rv, o);
      if (lane == 0) sm.red[w] = rv;
    } else if (lane == 0) {
      sm.red[w] = 0.0f;
    }
    if (tid < LMAX + 2) { sm.nb[0][tid] = NEGV; sm.nb[1][tid] = NEGV; }
    __syncthreads();
    if (tid == 0) {
      if (!bwd) sm.nb[0][1] = xb[sm.labs[0]];
      else      sm.nb[0][L] = 0.0f;
    }

    // ---- two-step-ahead x pipeline (per-thread float2 at j0)
    auto ldx = [&](int k) -> float2 {
      int tp = t0 + dt * k;
      tp = max(0, min(tp, T - 1));
      return *reinterpret_cast<const float2*>(xb + (size_t)tp * C + j0);
    };
    float2 xq0 = ldx(0);   // x[t_k]   at k=0
    float2 xq1 = ldx(1);   // x[t_{k+1}]

    float logS = 0.0f;
    int   cur  = 0;
    float wn0 = 0.0f, wn1 = 0.0f;

    const bool isnum = (h == 1);
    const int  lnum  = jp;
    int lab0 = 0, lab1 = -1;
    if (isnum && lnum < L) {
      lab0 = sm.labs[lnum];
      lab1 = (lnum + 1 < L) ? sm.labs[lnum + 1] : -1;
    }

    const int prdoff = 336 * h;            // copy h, c offset 64h (16B aligned)
    const int pwroff = h * P16PITCH + j0;

    for (int k = 0; k < nsteps; ++k) {
      __syncthreads();   // p16[cur], xt[cur], nb[cur], red visible
      const bool more = (k + 1) < nsteps;
      const int  nxt  = cur ^ 1;

      float2 xq2 = ldx(k + 2);   // consumed at step k+2 — ~2 steps of latency cover

      // ---- lagged normalizer (previous step's sum)
      float S = sm.red[lane & 15];
      #pragma unroll
      for (int o = 8; o; o >>= 1) S += __shfl_xor_sync(0xffffffffu, S, o);
      float rs = __fdividef(1.0f, S);

      // ---- GEMV quarter: 8 LDS.128 of p16 + 64 HFMA2, 4 accumulators per j
      const uint4* ph = reinterpret_cast<const uint4*>(sm.p16[cur] + prdoff);
      __half2 z = __float2half2_rn(0.0f);
      __half2 a0 = z, a1 = z, a2 = z, a3 = z;
      __half2 b0 = z, b1 = z, b2 = z, b3 = z;
      #pragma unroll
      for (int q = 0; q < 8; ++q) {
        uint4 pm = ph[q];
        const __half2* p2 = reinterpret_cast<const __half2*>(&pm);
        a0 = __hfma2(p2[0], mA[4 * q + 0], a0);
        a1 = __hfma2(p2[1], mA[4 * q + 1], a1);
        a2 = __hfma2(p2[2], mA[4 * q + 2], a2);
        a3 = __hfma2(p2[3], mA[4 * q + 3], a3);
        b0 = __hfma2(p2[0], mB[4 * q + 0], b0);
        b1 = __hfma2(p2[1], mB[4 * q + 1], b1);
        b2 = __hfma2(p2[2], mB[4 * q + 2], b2);
        b3 = __hfma2(p2[3], mB[4 * q + 3], b3);
      }
      a0 = __hadd2(a0, a1);  a2 = __hadd2(a2, a3);  a0 = __hadd2(a0, a2);
      b0 = __hadd2(b0, b1);  b2 = __hadd2(b2, b3);  b0 = __hadd2(b0, b2);
      float2 fa = __half22float2(a0);
      float2 fb = __half22float2(b0);
      float y0 = fa.x + fa.y;
      float y1 = fb.x + fb.y;
      // combine 4 h-quarters (symmetric: every lane ends with the full sum)
      y0 += __shfl_xor_sync(0xffffffffu, y0, 1);
      y0 += __shfl_xor_sync(0xffffffffu, y0, 2);
      y1 += __shfl_xor_sync(0xffffffffu, y1, 1);
      y1 += __shfl_xor_sync(0xffffffffu, y1, 2);

      if (!bwd) {
        wn0 = y0 * __expf(xq0.x) * rs;
        wn1 = y1 * __expf(xq0.y) * rs;
      } else {
        wn0 = y0 * rs;
        wn1 = y1 * rs;
        if (more) { wn0 *= __expf(xq1.x); wn1 *= __expf(xq1.y); }
      }
      *reinterpret_cast<__half2*>(&sm.p16[nxt][pwroff]) =
          __floats2half2_rn(wn0, wn1);

      { // per-step red (h==0 contributes)
        float rv = (h == 0) ? (wn0 + wn1) : 0.0f;
        rv += __shfl_xor_sync(0xffffffffu, rv, 4);
        rv += __shfl_xor_sync(0xffffffffu, rv, 8);
        rv += __shfl_xor_sync(0xffffffffu, rv, 16);
        if (lane == 0) sm.red[w] = rv;
      }

      if (h == 2 && more)
        *reinterpret_cast<float2*>(&sm.xt[nxt][j0]) = xq1;   // x[t_{k+1}]

      if (isnum && lnum < L) {
        int l = lnum;
        float nnew;
        if (!bwd) {
          float e = sm.xt[cur][lab0];
          nnew = lse2_fast(sm.nb[cur][l + 1], sm.nb[cur][l]) + e;
        } else {
          float v0 = sm.nb[cur][l + 1] + sm.xt[cur][lab0];
          float v1 = NEGV;
          if (lab1 >= 0) v1 = sm.nb[cur][l + 2] + sm.xt[cur][lab1];
          nnew = lse2_fast(v0, v1);
        }
        sm.nb[nxt][l + 1] = nnew;
      }

      if (tid == 0) logS += __logf(S);

      xq0 = xq1; xq1 = xq2;
      cur ^= 1;
    }
    __syncthreads();

    float Sf = sm.red[lane & 15];
    #pragma unroll
    for (int o = 8; o; o >>= 1) Sf += __shfl_xor_sync(0xffffffffu, Sf, o);

    if (!bwd) {
      if (h == 0) {   // final w held in registers (identical across h lanes)
        g_f[b][j0] = wn0 / Sf;
        g_f[b][j1] = wn1 / Sf;
      }
      if (tid < L)  g_a[b][tid] = sm.nb[cur][tid + 1];
      if (tid == 0) g_lsf[b] = logS + logf(Sf);
    } else {
      if (h == 0) {
        g_g[b][j0] = wn0 / Sf;
        g_g[b][j1] = wn1 / Sf;
      }
      if (tid < L)  g_bt[b][tid] = sm.nb[cur][tid + 1];
      if (tid == 0) g_lsg[b] = logS + logf(Sf);
    }
    __syncthreads();
  }

  // ---- last-CTA-done: the final arriver performs the combine ----
  if (tid == 0) {
    __threadfence();                       // release g_f/g_a/g_lsf...
    int ticket = atomicAdd(&g_bar, 1);
    sm.amLast = (ticket == grid - 1);
  }
  __syncthreads();
  if (!sm.amLast) return;
  __threadfence();                         // acquire others' writes

  // combine (512 threads, warp per batch)
  for (int b2 = w; b2 < B; b2 += 16) {
    float dot = 0.0f;
    for (int c = lane; c < C; c += 32) dot += g_f[b2][c] * g_g[b2][c];
    #pragma unroll
    for (int o = 16; o; o >>= 1) dot += __shfl_xor_sync(0xffffffffu, dot, o);

    float mx = -INFINITY;
    for (int l = lane; l < L; l += 32) mx = fmaxf(mx, g_a[b2][l] + g_bt[b2][l]);
    #pragma unroll
    for (int o = 16; o; o >>= 1) mx = fmaxf(mx, __shfl_xor_sync(0xffffffffu, mx, o));

    float s = 0.0f;
    for (int l = lane; l < L; l += 32) s += expf(g_a[b2][l] + g_bt[b2][l] - mx);
    #pragma unroll
    for (int o = 16; o; o >>= 1) s += __shfl_xor_sync(0xffffffffu, s, o);

    if (lane == 0) {
      float num = mx + logf(s);
      float den = logf(dot) + g_lsf[b2] + g_lsg[b2];
      sm.sc[b2] = num - den;
    }
  }
  __syncthreads();
  if (tid == 0) {
    float tot = 0.0f;
    for (int i = 0; i < B; ++i) tot += sm.sc[i];   // fixed order => deterministic
    long long fr = 0;
    for (int i = 0; i < B; ++i) fr += durations[i];
    out[0] = tot;
    if (out_size > 1) out[1] = (float)fr;
    if (out_size > 2) out[2] = (float)fr;
    g_bar = 0;                                     // reset for next (graph) call
    __threadfence();
  }
}

extern "C" void kernel_launch(void* const* d_in, const int* in_sizes, int n_in,
                              void* d_out, int out_size)
{
  const float* x      = (const float*)d_in[0];
  const float* trans  = (const float*)d_in[1];
  const int*   labels = (const int*)d_in[2];
  const int*   dur    = (const int*)d_in[3];

  int B = in_sizes[3];
  int L = in_sizes[2] / B;
  int T = in_sizes[0] / (B * C);
  int nwork = 2 * B;
  int grid  = nwork < GRID_PAD ? GRID_PAD : nwork;

  size_t smem = sizeof(SmemLayout);
  cudaFuncSetAttribute(chain_kernel, cudaFuncAttributeMaxDynamicSharedMemorySize, (int)smem);

  chain_kernel<<<grid, THREADS, smem>>>(x, trans, labels, dur, T, L,
                                        nwork, grid, B, (float*)d_out, out_size);
}